// round 1
// baseline (speedup 1.0000x reference)
#include <cuda_runtime.h>

#define CIN   128
#define CHID  256
#define COUT  128
#define HW    1600
#define TP    128
#define NT    256
#define NTILE 13   // ceil(1600/128)

// Normalized expert indices (handles int64-or-int32 serialized `indices`)
__device__ int g_idx[256];

__global__ void prep_idx(const int* __restrict__ raw) {
    __shared__ int odd_nz;
    if (threadIdx.x == 0) odd_nz = 0;
    __syncthreads();
    // If the buffer is int64 little-endian with values 0..7, every odd int32
    // word is zero. If it's int32, odd words are random 0..7 -> almost surely
    // at least one nonzero among 128.
    if (threadIdx.x < 128) {
        if (raw[2 * threadIdx.x + 1] != 0) atomicAdd(&odd_nz, 1);
    }
    __syncthreads();
    bool is64 = (odd_nz == 0);
    g_idx[threadIdx.x] = is64 ? raw[2 * threadIdx.x] : raw[threadIdx.x];
}

// Fused MoE: per (batch, pixel-tile) CTA, for each of the 2 selected experts:
//   h = gate * silu(W1 @ x + b1)   (gate folded into h by linearity)
//   out += W2 @ h ; out += gate * b2
__global__ __launch_bounds__(NT, 1)
void moe_kernel(const float* __restrict__ x,
                const float* __restrict__ gate_w,
                const float* __restrict__ W1,
                const float* __restrict__ b1,
                const float* __restrict__ W2,
                const float* __restrict__ b2,
                float* __restrict__ out)
{
    extern __shared__ float sm[];
    float* xs = sm;                    // [128 c][128 p]           = 16384 f
    float* hs = xs + CIN * TP;         // [64 k][132 p] (padded)   =  8448 f
    float* ws = hs + 64 * 132;         // union: W1 chunk [64][128] / W2 chunk [128][64] = 8192 f

    const int tid = threadIdx.x;
    const int tx  = tid & 15;   // pixel direction (8 px per thread)
    const int ty  = tid >> 4;   // out-channel direction
    const int b   = blockIdx.y;
    const int p0  = blockIdx.x * TP;

    // ---- load x tile (coalesced), zero-pad OOB pixels ----
    const float* xb = x + (size_t)b * CIN * HW;
    for (int idx = tid; idx < CIN * TP; idx += NT) {
        int c = idx >> 7, p = idx & 127;
        int pg = p0 + p;
        xs[idx] = (pg < HW) ? xb[c * HW + pg] : 0.0f;
    }
    __syncthreads();

    float outA[8][8];
    #pragma unroll
    for (int i = 0; i < 8; i++)
        #pragma unroll
        for (int j = 0; j < 8; j++) outA[i][j] = 0.0f;

    #pragma unroll 1
    for (int k = 0; k < 2; k++) {
        const int   e = g_idx[b * 2 + k];
        const float g = gate_w[b * 2 + k];
        const float* W1e = W1 + (size_t)e * CHID * CIN;
        const float* W2e = W2 + (size_t)e * COUT * CHID;
        const float* b1e = b1 + e * CHID;
        const float* b2e = b2 + e * COUT;

        #pragma unroll 1
        for (int hc = 0; hc < 4; hc++) {
            // ---- stage W1 chunk [64 oc][128 c], natural layout, coalesced ----
            {
                const float* src = W1e + (size_t)(hc * 64) * CIN;
                for (int idx = tid; idx < 64 * CIN; idx += NT) ws[idx] = src[idx];
            }
            __syncthreads();

            // ---- GEMM1: hacc[4 oc][8 p] over c=0..127 ----
            float hacc[4][8];
            #pragma unroll
            for (int i = 0; i < 4; i++)
                #pragma unroll
                for (int j = 0; j < 8; j++) hacc[i][j] = 0.0f;

            #pragma unroll 2
            for (int c = 0; c < CIN; c++) {
                float a0 = ws[(ty * 4 + 0) * 128 + c];   // lane-uniform: broadcast
                float a1 = ws[(ty * 4 + 1) * 128 + c];
                float a2 = ws[(ty * 4 + 2) * 128 + c];
                float a3 = ws[(ty * 4 + 3) * 128 + c];
                float4 xv0 = *(const float4*)&xs[c * 128 + tx * 8];
                float4 xv1 = *(const float4*)&xs[c * 128 + tx * 8 + 4];
                float xr[8] = {xv0.x, xv0.y, xv0.z, xv0.w, xv1.x, xv1.y, xv1.z, xv1.w};
                #pragma unroll
                for (int j = 0; j < 8; j++) {
                    hacc[0][j] = fmaf(a0, xr[j], hacc[0][j]);
                    hacc[1][j] = fmaf(a1, xr[j], hacc[1][j]);
                    hacc[2][j] = fmaf(a2, xr[j], hacc[2][j]);
                    hacc[3][j] = fmaf(a3, xr[j], hacc[3][j]);
                }
            }

            // ---- bias + SiLU, pre-scaled by gate; store to hs ----
            #pragma unroll
            for (int i = 0; i < 4; i++) {
                float bias = __ldg(&b1e[hc * 64 + ty * 4 + i]);
                #pragma unroll
                for (int j = 0; j < 8; j++) {
                    float v = hacc[i][j] + bias;
                    float s = v / (1.0f + __expf(-v));
                    hs[(ty * 4 + i) * 132 + tx * 8 + j] = g * s;
                }
            }
            __syncthreads();   // ws reads done + hs fully written

            // ---- stage W2 chunk [128 oc][64 kk], natural layout, coalesced ----
            for (int idx = tid; idx < COUT * 64; idx += NT) {
                int oc = idx >> 6, kk = idx & 63;
                ws[idx] = W2e[oc * CHID + hc * 64 + kk];
            }
            __syncthreads();

            // ---- GEMM2: outA[8 oc][8 p] += W2chunk @ hs ----
            #pragma unroll 2
            for (int kk = 0; kk < 64; kk++) {
                float a[8];
                #pragma unroll
                for (int i = 0; i < 8; i++) a[i] = ws[(ty * 8 + i) * 64 + kk];  // broadcast
                float4 hv0 = *(const float4*)&hs[kk * 132 + tx * 8];
                float4 hv1 = *(const float4*)&hs[kk * 132 + tx * 8 + 4];
                float hr[8] = {hv0.x, hv0.y, hv0.z, hv0.w, hv1.x, hv1.y, hv1.z, hv1.w};
                #pragma unroll
                for (int i = 0; i < 8; i++)
                    #pragma unroll
                    for (int j = 0; j < 8; j++)
                        outA[i][j] = fmaf(a[i], hr[j], outA[i][j]);
            }
            __syncthreads();   // hs+ws consumed before next chunk overwrites
        }

        // ---- out += gate * b2[e] ----
        #pragma unroll
        for (int i = 0; i < 8; i++) {
            float bb = g * __ldg(&b2e[ty * 8 + i]);
            #pragma unroll
            for (int j = 0; j < 8; j++) outA[i][j] += bb;
        }
    }

    // ---- store (guard partial last tile; float4 groups are all-in or all-out
    //      only at 4-granularity, so guard each quad) ----
    float* ob = out + (size_t)b * COUT * HW;
    #pragma unroll
    for (int i = 0; i < 8; i++) {
        int oc = ty * 8 + i;
        #pragma unroll
        for (int j0 = 0; j0 < 8; j0 += 4) {
            int pg = p0 + tx * 8 + j0;
            if (pg + 3 < HW) {
                float4 v = make_float4(outA[i][j0], outA[i][j0 + 1],
                                       outA[i][j0 + 2], outA[i][j0 + 3]);
                *(float4*)&ob[oc * HW + pg] = v;
            } else {
                for (int j = j0; j < j0 + 4; j++) {
                    int p = p0 + tx * 8 + j;
                    if (p < HW) ob[oc * HW + p] = outA[i][j];
                }
            }
        }
    }
}

extern "C" void kernel_launch(void* const* d_in, const int* in_sizes, int n_in,
                              void* d_out, int out_size) {
    const float* x   = (const float*)d_in[0];
    const float* wts = (const float*)d_in[1];
    const int*   idx = (const int*)d_in[2];
    const float* W1  = (const float*)d_in[3];
    const float* b1  = (const float*)d_in[4];
    const float* W2  = (const float*)d_in[5];
    const float* b2  = (const float*)d_in[6];
    float* out = (float*)d_out;

    (void)in_sizes; (void)n_in; (void)out_size;

    prep_idx<<<1, 256>>>(idx);

    const int smem_bytes = (CIN * TP + 64 * 132 + 64 * 128) * (int)sizeof(float); // 132096
    cudaFuncSetAttribute(moe_kernel, cudaFuncAttributeMaxDynamicSharedMemorySize, smem_bytes);

    dim3 grid(NTILE, 128);
    moe_kernel<<<grid, NT, smem_bytes>>>(x, wts, W1, b1, W2, b2, out);
}

// round 3
// speedup vs baseline: 2.4953x; 2.4953x over previous
#include <cuda_runtime.h>
#include <cuda_bf16.h>
#include <cstdint>

#define CIN   128
#define CHID  256
#define COUT  128
#define HW    1600
#define TP    128
#define NT    256
#define NTILE 13

// ---- SMEM byte offsets ----
#define XS_HI 0          // x^T hi [128 px][128 c] bf16, row stride 272B
#define XS_LO 34816
#define W1_HI 69632      // W1 chunk [64 ch][128 c], stride 272B
#define W1_LO 87040
#define HS_HI 104448     // h chunk [128 px][64 ch], stride 144B
#define HS_LO 122880
#define W2_HI 141312     // W2 chunk [128 oc][64 ch], stride 144B
#define W2_LO 159744
#define B1S   178176     // b1 chunk, 64 f32
#define GB2   178432     // gated b2, 128 f32
#define SM_TOTAL 178944

#define SX 272           // 128 bf16 + 8 pad  (68 words/row: conflict-free ldmatrix)
#define SH 144           // 64 bf16 + 8 pad   (36 words/row: conflict-free ldmatrix)

__device__ __forceinline__ uint32_t smem_u32(const void* p) {
    uint32_t a;
    asm("{ .reg .u64 t; cvta.to.shared.u64 t, %1; cvt.u32.u64 %0, t; }" : "=r"(a) : "l"(p));
    return a;
}
__device__ __forceinline__ void ldsm4(uint32_t (&r)[4], uint32_t a) {
    asm volatile("ldmatrix.sync.aligned.m8n8.x4.shared.b16 {%0,%1,%2,%3}, [%4];"
                 : "=r"(r[0]), "=r"(r[1]), "=r"(r[2]), "=r"(r[3]) : "r"(a));
}
__device__ __forceinline__ void mma16816(float (&d)[4], const uint32_t (&a)[4],
                                         uint32_t b0, uint32_t b1) {
    asm volatile(
        "mma.sync.aligned.m16n8k16.row.col.f32.bf16.bf16.f32 "
        "{%0,%1,%2,%3}, {%4,%5,%6,%7}, {%8,%9}, {%0,%1,%2,%3};"
        : "+f"(d[0]), "+f"(d[1]), "+f"(d[2]), "+f"(d[3])
        : "r"(a[0]), "r"(a[1]), "r"(a[2]), "r"(a[3]), "r"(b0), "r"(b1));
}
__device__ __forceinline__ uint32_t pk(unsigned short a, unsigned short b) {
    return (uint32_t)a | ((uint32_t)b << 16);
}
__device__ __forceinline__ void bsplit(float v, unsigned short& h, unsigned short& l) {
    __nv_bfloat16 hb = __float2bfloat16(v);
    h = __bfloat16_as_ushort(hb);
    l = __bfloat16_as_ushort(__float2bfloat16(v - __bfloat162float(hb)));
}

__device__ int g_idx[256];

__global__ void prep_idx(const int* __restrict__ raw) {
    __shared__ int odd_nz;
    if (threadIdx.x == 0) odd_nz = 0;
    __syncthreads();
    if (threadIdx.x < 128) {
        if (raw[2 * threadIdx.x + 1] != 0) atomicAdd(&odd_nz, 1);
    }
    __syncthreads();
    bool is64 = (odd_nz == 0);
    g_idx[threadIdx.x] = is64 ? raw[2 * threadIdx.x] : raw[threadIdx.x];
}

__global__ __launch_bounds__(NT, 1)
void moe_mma(const float* __restrict__ x,
             const float* __restrict__ gate_w,
             const float* __restrict__ W1,
             const float* __restrict__ b1,
             const float* __restrict__ W2,
             const float* __restrict__ b2,
             float* __restrict__ out)
{
    extern __shared__ char sm[];
    const uint32_t smb = smem_u32(sm);
    const int tid  = threadIdx.x;
    const int lane = tid & 31;
    const int w    = tid >> 5;          // warp id: owns px rows [16w, 16w+16)
    const int b    = blockIdx.y;
    const int p0   = blockIdx.x * TP;

    const int   e0 = g_idx[b * 2],          e1 = g_idx[b * 2 + 1];
    const float g0 = __ldg(&gate_w[b * 2]), g1 = __ldg(&gate_w[b * 2 + 1]);

    // ---- gated b2 (read in final epilogue only) ----
    if (tid < 128) {
        float v = g0 * __ldg(&b2[e0 * COUT + tid]) + g1 * __ldg(&b2[e1 * COUT + tid]);
        *(float*)(sm + GB2 + 4 * tid) = v;
    }

    // ---- stage x^T hi/lo: [px][c], row stride SX ----
    {
        const float* xb = x + (size_t)b * CIN * HW + p0;
        for (int e2 = tid; e2 < 8192; e2 += NT) {
            int c = (e2 >> 7) * 2, p = e2 & 127;
            float a = 0.f, v = 0.f;
            if (p0 + p < HW) { a = xb[(size_t)c * HW + p]; v = xb[(size_t)(c + 1) * HW + p]; }
            unsigned short ah, al, vh, vl;
            bsplit(a, ah, al); bsplit(v, vh, vl);
            uint32_t off = (uint32_t)(p * SX + c * 2);
            *(uint32_t*)(sm + XS_HI + off) = pk(ah, vh);
            *(uint32_t*)(sm + XS_LO + off) = pk(al, vl);
        }
    }

    // ldmatrix per-lane address offsets
    const uint32_t loA1 = (uint32_t)((lane & 15) * SX + (lane >> 4) * 16);
    const uint32_t loB1 = (uint32_t)(((lane & 7) + (lane >> 4) * 8) * SX + ((lane >> 3) & 1) * 16);
    const uint32_t loA2 = (uint32_t)((lane & 15) * SH + (lane >> 4) * 16);
    const uint32_t loB2 = (uint32_t)(((lane & 7) + (lane >> 4) * 8) * SH + ((lane >> 3) & 1) * 16);

    float acc2[16][4];
    #pragma unroll
    for (int i = 0; i < 16; i++)
        #pragma unroll
        for (int q = 0; q < 4; q++) acc2[i][q] = 0.f;

    const int g4 = lane >> 2, t2 = (lane & 3) * 2;

    #pragma unroll 1
    for (int it = 0; it < 8; it++) {
        const int   slot = it >> 2, j = it & 3;
        const int   e = (slot == 0) ? e0 : e1;
        const float g = (slot == 0) ? g0 : g1;

        // ---- stage W1 chunk [64 ch][128 c] hi/lo + b1 chunk ----
        {
            const float* w1p = W1 + (size_t)e * CHID * CIN + (size_t)(j * 64) * CIN;
            for (int f4 = tid; f4 < 2048; f4 += NT) {
                int r = f4 >> 5, c = (f4 & 31) * 4;
                float4 wv = *(const float4*)(w1p + r * CIN + c);
                unsigned short h0,l0,h1,l1,h2,l2,h3,l3;
                bsplit(wv.x,h0,l0); bsplit(wv.y,h1,l1); bsplit(wv.z,h2,l2); bsplit(wv.w,h3,l3);
                uint32_t off = (uint32_t)(r * SX + c * 2);
                *(uint2*)(sm + W1_HI + off) = make_uint2(pk(h0,h1), pk(h2,h3));
                *(uint2*)(sm + W1_LO + off) = make_uint2(pk(l0,l1), pk(l2,l3));
            }
            if (tid < 64) ((float*)(sm + B1S))[tid] = __ldg(&b1[e * CHID + j * 64 + tid]);
        }
        __syncthreads();

        // ---- GEMM1: h[16px strip][64ch] = x^T @ W1^T (split bf16, 3 MMAs) ----
        float acc1[8][4];
        #pragma unroll
        for (int i = 0; i < 8; i++)
            #pragma unroll
            for (int q = 0; q < 4; q++) acc1[i][q] = 0.f;

        #pragma unroll
        for (int k = 0; k < 8; k++) {
            uint32_t ah[4], al[4];
            uint32_t abase = smb + (uint32_t)(w * 16 * SX + k * 32);
            ldsm4(ah, abase + XS_HI + loA1);
            ldsm4(al, abase + XS_LO + loA1);
            #pragma unroll
            for (int np = 0; np < 4; np++) {
                uint32_t bh[4], bl[4];
                uint32_t bbase = smb + (uint32_t)(np * 16 * SX + k * 32);
                ldsm4(bh, bbase + W1_HI + loB1);
                ldsm4(bl, bbase + W1_LO + loB1);
                mma16816(acc1[2*np],   ah, bh[0], bh[1]);
                mma16816(acc1[2*np],   ah, bl[0], bl[1]);
                mma16816(acc1[2*np],   al, bh[0], bh[1]);
                mma16816(acc1[2*np+1], ah, bh[2], bh[3]);
                mma16816(acc1[2*np+1], ah, bl[2], bl[3]);
                mma16816(acc1[2*np+1], al, bh[2], bh[3]);
            }
        }

        // ---- epilogue: bias + SiLU + gate, bf16-split -> h smem ----
        {
            const float* b1s = (const float*)(sm + B1S);
            int pxr0 = w * 16 + g4;
            #pragma unroll
            for (int nt = 0; nt < 8; nt++) {
                int ch = nt * 8 + t2;
                float bi0 = b1s[ch], bi1 = b1s[ch + 1];
                #pragma unroll
                for (int half = 0; half < 2; half++) {
                    float v0 = acc1[nt][2*half]     + bi0;
                    float v1 = acc1[nt][2*half + 1] + bi1;
                    float h0 = g * (v0 / (1.f + __expf(-v0)));
                    float h1 = g * (v1 / (1.f + __expf(-v1)));
                    unsigned short a0, a1, c0, c1;
                    bsplit(h0, a0, a1); bsplit(h1, c0, c1);
                    uint32_t off = (uint32_t)((pxr0 + half * 8) * SH + ch * 2);
                    *(uint32_t*)(sm + HS_HI + off) = pk(a0, c0);
                    *(uint32_t*)(sm + HS_LO + off) = pk(a1, c1);
                }
            }
        }

        // ---- stage W2 chunk [128 oc][64 ch] hi/lo (buffer free since last sync) ----
        {
            const float* w2p = W2 + (size_t)e * COUT * CHID + j * 64;
            for (int f4 = tid; f4 < 2048; f4 += NT) {
                int r = f4 >> 4, c = (f4 & 15) * 4;
                float4 wv = *(const float4*)(w2p + (size_t)r * CHID + c);
                unsigned short h0,l0,h1,l1,h2,l2,h3,l3;
                bsplit(wv.x,h0,l0); bsplit(wv.y,h1,l1); bsplit(wv.z,h2,l2); bsplit(wv.w,h3,l3);
                uint32_t off = (uint32_t)(r * SH + c * 2);
                *(uint2*)(sm + W2_HI + off) = make_uint2(pk(h0,h1), pk(h2,h3));
                *(uint2*)(sm + W2_LO + off) = make_uint2(pk(l0,l1), pk(l2,l3));
            }
        }
        __syncthreads();

        // ---- GEMM2: out[16px strip][128oc] += h @ W2^T ----
        #pragma unroll
        for (int k = 0; k < 4; k++) {
            uint32_t ah[4], al[4];
            uint32_t abase = smb + (uint32_t)(w * 16 * SH + k * 32);
            ldsm4(ah, abase + HS_HI + loA2);
            ldsm4(al, abase + HS_LO + loA2);
            #pragma unroll
            for (int np = 0; np < 8; np++) {
                uint32_t bh[4], bl[4];
                uint32_t bbase = smb + (uint32_t)(np * 16 * SH + k * 32);
                ldsm4(bh, bbase + W2_HI + loB2);
                ldsm4(bl, bbase + W2_LO + loB2);
                mma16816(acc2[2*np],   ah, bh[0], bh[1]);
                mma16816(acc2[2*np],   ah, bl[0], bl[1]);
                mma16816(acc2[2*np],   al, bh[0], bh[1]);
                mma16816(acc2[2*np+1], ah, bh[2], bh[3]);
                mma16816(acc2[2*np+1], ah, bl[2], bl[3]);
                mma16816(acc2[2*np+1], al, bh[2], bh[3]);
            }
        }
        __syncthreads();   // h + W2 (+W1/x reads) quiesced before next-iter staging
    }

    // ---- final store: acc2 + gated b2 -> out[b][oc][px] ----
    {
        const float* gb2 = (const float*)(sm + GB2);
        float* ob = out + (size_t)b * COUT * HW;
        int px0 = p0 + w * 16 + g4;
        #pragma unroll
        for (int nt = 0; nt < 16; nt++) {
            int oc = nt * 8 + t2;
            float gv0 = gb2[oc], gv1 = gb2[oc + 1];
            if (px0 < HW) {
                ob[(size_t)oc * HW + px0]       = acc2[nt][0] + gv0;
                ob[(size_t)(oc + 1) * HW + px0] = acc2[nt][1] + gv1;
            }
            if (px0 + 8 < HW) {
                ob[(size_t)oc * HW + px0 + 8]       = acc2[nt][2] + gv0;
                ob[(size_t)(oc + 1) * HW + px0 + 8] = acc2[nt][3] + gv1;
            }
        }
    }
}

extern "C" void kernel_launch(void* const* d_in, const int* in_sizes, int n_in,
                              void* d_out, int out_size) {
    const float* x   = (const float*)d_in[0];
    const float* wts = (const float*)d_in[1];
    const int*   idx = (const int*)d_in[2];
    const float* W1  = (const float*)d_in[3];
    const float* b1  = (const float*)d_in[4];
    const float* W2  = (const float*)d_in[5];
    const float* b2  = (const float*)d_in[6];
    float* out = (float*)d_out;
    (void)in_sizes; (void)n_in; (void)out_size;

    prep_idx<<<1, 256>>>(idx);

    cudaFuncSetAttribute(moe_mma, cudaFuncAttributeMaxDynamicSharedMemorySize, SM_TOTAL);
    dim3 grid(NTILE, 128);
    moe_mma<<<grid, NT, SM_TOTAL>>>(x, wts, W1, b1, W2, b2, out);
}

// round 4
// speedup vs baseline: 3.4515x; 1.3832x over previous
#include <cuda_runtime.h>
#include <cstdint>

#define CIN   128
#define CHID  256
#define COUT  128
#define HW    1600
#define TP    128
#define NT    256
#define NTILE 13

// SMEM float offsets (row strides 132/68 ≡ 4 mod 32 -> conflict-free fragment LDS)
#define OXS 0          // x^T [128 p][132] tf32
#define OW1 16896      // W1 chunk [64 ch][132]
#define OW2 25344      // W2 chunk [128 oc][68]
#define OHS 34048      // h chunk  [128 p][68]
#define OGB 42752      // gated b2 [128]
#define SMB (42880 * 4)

__device__ __forceinline__ float tf32f(float v) {
    uint32_t r;
    asm("cvt.rna.tf32.f32 %0, %1;" : "=r"(r) : "f"(v));
    return __uint_as_float(r);
}

__device__ __forceinline__ void mma8(float (&d)[4], const float (&a)[4], float b0, float b1) {
    asm("mma.sync.aligned.m16n8k8.row.col.f32.tf32.tf32.f32 "
        "{%0,%1,%2,%3}, {%4,%5,%6,%7}, {%8,%9}, {%0,%1,%2,%3};"
        : "+f"(d[0]), "+f"(d[1]), "+f"(d[2]), "+f"(d[3])
        : "r"(__float_as_uint(a[0])), "r"(__float_as_uint(a[1])),
          "r"(__float_as_uint(a[2])), "r"(__float_as_uint(a[3])),
          "r"(__float_as_uint(b0)),  "r"(__float_as_uint(b1)));
}

__device__ int g_idx[256];

__global__ void prep_idx(const int* __restrict__ raw) {
    __shared__ int odd_nz;
    if (threadIdx.x == 0) odd_nz = 0;
    __syncthreads();
    if (threadIdx.x < 128) {
        if (raw[2 * threadIdx.x + 1] != 0) atomicAdd(&odd_nz, 1);
    }
    __syncthreads();
    bool is64 = (odd_nz == 0);
    g_idx[threadIdx.x] = is64 ? raw[2 * threadIdx.x] : raw[threadIdx.x];
}

__global__ __launch_bounds__(NT, 1)
void moe_tf32(const float* __restrict__ x,
              const float* __restrict__ gate_w,
              const float* __restrict__ W1,
              const float* __restrict__ b1,
              const float* __restrict__ W2,
              const float* __restrict__ b2,
              float* __restrict__ out)
{
    extern __shared__ float sm[];
    const int tid  = threadIdx.x;
    const int lane = tid & 31;
    const int warp = tid >> 5;
    const int wm   = warp >> 1;          // 0..3: M group (32 px)
    const int wn   = warp & 1;           // 0..1: N group
    const int g    = lane >> 2;          // groupID
    const int t    = lane & 3;           // threadID in group
    const int b    = blockIdx.y;
    const int p0   = blockIdx.x * TP;
    const int R0   = wm * 32;

    const int   e0 = g_idx[b * 2],           e1 = g_idx[b * 2 + 1];
    const float g0 = __ldg(&gate_w[b * 2]);
    const float g1 = __ldg(&gate_w[b * 2 + 1]);

    if (tid < 128)
        sm[OGB + tid] = g0 * __ldg(&b2[e0 * COUT + tid]) + g1 * __ldg(&b2[e1 * COUT + tid]);

    // ---- stage x^T (transpose via 4x4 register tiles; conflict-free STS.128) ----
    {
        const float* xb = x + (size_t)b * CIN * HW + p0;
        const int q  = tid & 7;          // c-group phase
        const int pp = tid >> 3;         // p-group 0..31
        const int pv = 4 * pp;
        #pragma unroll
        for (int cc = 0; cc < 4; cc++) {
            const int cg = 4 * (q + 8 * cc);      // c base (mult of 4)
            float4 v0, v1, v2, v3;
            if (p0 + pv < HW) {
                v0 = *(const float4*)(xb + (size_t)(cg + 0) * HW + pv);
                v1 = *(const float4*)(xb + (size_t)(cg + 1) * HW + pv);
                v2 = *(const float4*)(xb + (size_t)(cg + 2) * HW + pv);
                v3 = *(const float4*)(xb + (size_t)(cg + 3) * HW + pv);
            } else {
                v0 = v1 = v2 = v3 = make_float4(0.f, 0.f, 0.f, 0.f);
            }
            float4 s;
            s = make_float4(tf32f(v0.x), tf32f(v1.x), tf32f(v2.x), tf32f(v3.x));
            *(float4*)(sm + OXS + (pv + 0) * 132 + cg) = s;
            s = make_float4(tf32f(v0.y), tf32f(v1.y), tf32f(v2.y), tf32f(v3.y));
            *(float4*)(sm + OXS + (pv + 1) * 132 + cg) = s;
            s = make_float4(tf32f(v0.z), tf32f(v1.z), tf32f(v2.z), tf32f(v3.z));
            *(float4*)(sm + OXS + (pv + 2) * 132 + cg) = s;
            s = make_float4(tf32f(v0.w), tf32f(v1.w), tf32f(v2.w), tf32f(v3.w));
            *(float4*)(sm + OXS + (pv + 3) * 132 + cg) = s;
        }
    }

    // bias column offsets for this lane (fixed across iters)
    int colv[8];
    #pragma unroll
    for (int u = 0; u < 8; u++) colv[u] = (u >> 1) * 8 + 2 * t + (u & 1);

    // ---- prefetch chunk 0 into registers ----
    float4 w1r[8], w2r[8];
    float biasv[8];
    {
        const float* w1p = W1 + (size_t)e0 * CHID * CIN;
        const float* w2p = W2 + (size_t)e0 * COUT * CHID;
        #pragma unroll
        for (int i = 0; i < 8; i++) {
            int f = tid + i * NT;
            w1r[i] = *(const float4*)(w1p + (size_t)(f >> 5) * CIN + (f & 31) * 4);
            w2r[i] = *(const float4*)(w2p + (size_t)(f >> 4) * CHID + (f & 15) * 4);
        }
        #pragma unroll
        for (int u = 0; u < 8; u++)
            biasv[u] = __ldg(b1 + e0 * CHID + wn * 32 + colv[u]);
    }

    float acc2[2][8][4];
    #pragma unroll
    for (int m = 0; m < 2; m++)
        #pragma unroll
        for (int j = 0; j < 8; j++)
            #pragma unroll
            for (int q = 0; q < 4; q++) acc2[m][j][q] = 0.f;

    __syncthreads();   // x staged (W buffers not yet read)

    #pragma unroll 1
    for (int it = 0; it < 8; it++) {
        const float gcur = (it < 4) ? g0 : g1;
        const int   itn  = it + 1;
        const int   en   = (itn >= 4) ? e1 : e0;
        const int   jn   = itn & 3;

        // ---- commit prefetched W chunks to SMEM (conflict-free STS.128) ----
        #pragma unroll
        for (int i = 0; i < 8; i++) {
            int f = tid + i * NT;
            float4 v = w1r[i];
            *(float4*)(sm + OW1 + (f >> 5) * 132 + (f & 31) * 4) =
                make_float4(tf32f(v.x), tf32f(v.y), tf32f(v.z), tf32f(v.w));
            v = w2r[i];
            *(float4*)(sm + OW2 + (f >> 4) * 68 + (f & 15) * 4) =
                make_float4(tf32f(v.x), tf32f(v.y), tf32f(v.z), tf32f(v.w));
        }
        __syncthreads();   // W1S/W2S visible

        // ---- prefetch next W1 + bias (latency hidden by GEMM1) ----
        float biasn[8];
        if (it < 7) {
            const float* w1p = W1 + (size_t)en * CHID * CIN + (size_t)(jn * 64) * CIN;
            #pragma unroll
            for (int i = 0; i < 8; i++) {
                int f = tid + i * NT;
                w1r[i] = *(const float4*)(w1p + (size_t)(f >> 5) * CIN + (f & 31) * 4);
            }
            #pragma unroll
            for (int u = 0; u < 8; u++)
                biasn[u] = __ldg(b1 + en * CHID + jn * 64 + wn * 32 + colv[u]);
        }

        // ---- GEMM1: acc1[32 px][32 ch] = x @ W1chunk^T ----
        float acc1[2][4][4];
        #pragma unroll
        for (int m = 0; m < 2; m++)
            #pragma unroll
            for (int j = 0; j < 4; j++)
                #pragma unroll
                for (int q = 0; q < 4; q++) acc1[m][j][q] = 0.f;

        #pragma unroll 4
        for (int k = 0; k < 16; k++) {
            float a[2][4];
            #pragma unroll
            for (int m = 0; m < 2; m++) {
                int r = R0 + m * 16 + g;
                a[m][0] = sm[OXS + r * 132 + 8 * k + t];
                a[m][1] = sm[OXS + (r + 8) * 132 + 8 * k + t];
                a[m][2] = sm[OXS + r * 132 + 8 * k + t + 4];
                a[m][3] = sm[OXS + (r + 8) * 132 + 8 * k + t + 4];
            }
            #pragma unroll
            for (int j = 0; j < 4; j++) {
                int n = wn * 32 + j * 8 + g;
                float b0 = sm[OW1 + n * 132 + 8 * k + t];
                float bq = sm[OW1 + n * 132 + 8 * k + t + 4];
                mma8(acc1[0][j], a[0], b0, bq);
                mma8(acc1[1][j], a[1], b0, bq);
            }
        }

        // ---- epilogue: bias + SiLU + gate -> h (tf32) ----
        #pragma unroll
        for (int m = 0; m < 2; m++) {
            #pragma unroll
            for (int j = 0; j < 4; j++) {
                #pragma unroll
                for (int hi = 0; hi < 2; hi++) {
                    float v0 = acc1[m][j][2 * hi]     + biasv[2 * j];
                    float v1 = acc1[m][j][2 * hi + 1] + biasv[2 * j + 1];
                    float h0 = gcur * (v0 / (1.f + __expf(-v0)));
                    float h1 = gcur * (v1 / (1.f + __expf(-v1)));
                    int row = R0 + m * 16 + g + 8 * hi;
                    int col = wn * 32 + j * 8 + 2 * t;
                    *(float2*)(sm + OHS + row * 68 + col) =
                        make_float2(tf32f(h0), tf32f(h1));
                }
            }
        }
        if (it < 7) {
            #pragma unroll
            for (int u = 0; u < 8; u++) biasv[u] = biasn[u];
            // prefetch next W2 (latency hidden by GEMM2)
            const float* w2p = W2 + (size_t)en * COUT * CHID + jn * 64;
            #pragma unroll
            for (int i = 0; i < 8; i++) {
                int f = tid + i * NT;
                w2r[i] = *(const float4*)(w2p + (size_t)(f >> 4) * CHID + (f & 15) * 4);
            }
        }
        __syncthreads();   // h visible to all warps

        // ---- GEMM2: acc2[32 px][64 oc] += h @ W2chunk^T ----
        #pragma unroll 4
        for (int k = 0; k < 8; k++) {
            float a[2][4];
            #pragma unroll
            for (int m = 0; m < 2; m++) {
                int r = R0 + m * 16 + g;
                a[m][0] = sm[OHS + r * 68 + 8 * k + t];
                a[m][1] = sm[OHS + (r + 8) * 68 + 8 * k + t];
                a[m][2] = sm[OHS + r * 68 + 8 * k + t + 4];
                a[m][3] = sm[OHS + (r + 8) * 68 + 8 * k + t + 4];
            }
            #pragma unroll
            for (int j = 0; j < 8; j++) {
                int n = wn * 64 + j * 8 + g;
                float b0 = sm[OW2 + n * 68 + 8 * k + t];
                float bq = sm[OW2 + n * 68 + 8 * k + t + 4];
                mma8(acc2[0][j], a[0], b0, bq);
                mma8(acc2[1][j], a[1], b0, bq);
            }
        }
        __syncthreads();   // W/h buffers free for next staging
    }

    // ---- final store: acc2 + gated b2 -> out ----
    {
        float* ob = out + (size_t)b * COUT * HW;
        #pragma unroll
        for (int m = 0; m < 2; m++) {
            #pragma unroll
            for (int hi = 0; hi < 2; hi++) {
                int pl = R0 + m * 16 + g + 8 * hi;
                if (p0 + pl < HW) {
                    #pragma unroll
                    for (int j = 0; j < 8; j++) {
                        int oc = wn * 64 + j * 8 + 2 * t;
                        ob[(size_t)oc * HW + p0 + pl] =
                            acc2[m][j][2 * hi] + sm[OGB + oc];
                        ob[(size_t)(oc + 1) * HW + p0 + pl] =
                            acc2[m][j][2 * hi + 1] + sm[OGB + oc + 1];
                    }
                }
            }
        }
    }
}

extern "C" void kernel_launch(void* const* d_in, const int* in_sizes, int n_in,
                              void* d_out, int out_size) {
    const float* x   = (const float*)d_in[0];
    const float* wts = (const float*)d_in[1];
    const int*   idx = (const int*)d_in[2];
    const float* W1  = (const float*)d_in[3];
    const float* b1  = (const float*)d_in[4];
    const float* W2  = (const float*)d_in[5];
    const float* b2  = (const float*)d_in[6];
    float* out = (float*)d_out;
    (void)in_sizes; (void)n_in; (void)out_size;

    prep_idx<<<1, 256>>>(idx);

    cudaFuncSetAttribute(moe_tf32, cudaFuncAttributeMaxDynamicSharedMemorySize, SMB);
    dim3 grid(NTILE, 128);
    moe_tf32<<<grid, NT, SMB>>>(x, wts, W1, b1, W2, b2, out);
}

// round 5
// speedup vs baseline: 3.8834x; 1.1251x over previous
#include <cuda_runtime.h>
#include <cstdint>

#define CIN   128
#define CHID  256
#define COUT  128
#define HW    1600
#define TP    128
#define NT    512
#define NTILE 13

// SMEM float offsets (row strides 132/68 == 4 mod 32 -> conflict-free fragment LDS)
#define OXS 0          // x^T [128 p][132] tf32
#define OW1 16896      // W1 chunk [64 ch][132] raw fp32 (cvt at fragment load)
#define OW2 25344      // W2 chunk [128 oc][68]
#define OHS 34048      // h chunk  [128 p][68] tf32
#define OGB 42752      // gated b2 [128]
#define SMB (42880 * 4)

__device__ __forceinline__ uint32_t smem_u32(const void* p) {
    uint32_t a;
    asm("{ .reg .u64 t; cvta.to.shared.u64 t, %1; cvt.u32.u64 %0, t; }" : "=r"(a) : "l"(p));
    return a;
}
__device__ __forceinline__ float tf32f(float v) {
    uint32_t r;
    asm("cvt.rna.tf32.f32 %0, %1;" : "=r"(r) : "f"(v));
    return __uint_as_float(r);
}
__device__ __forceinline__ void mma8(float (&d)[4], const float (&a)[4], float b0, float b1) {
    asm("mma.sync.aligned.m16n8k8.row.col.f32.tf32.tf32.f32 "
        "{%0,%1,%2,%3}, {%4,%5,%6,%7}, {%8,%9}, {%0,%1,%2,%3};"
        : "+f"(d[0]), "+f"(d[1]), "+f"(d[2]), "+f"(d[3])
        : "r"(__float_as_uint(a[0])), "r"(__float_as_uint(a[1])),
          "r"(__float_as_uint(a[2])), "r"(__float_as_uint(a[3])),
          "r"(__float_as_uint(b0)),  "r"(__float_as_uint(b1)));
}
#define CPA16(dst, src) asm volatile("cp.async.ca.shared.global [%0], [%1], 16;" :: "r"(dst), "l"(src))
#define CPA_COMMIT()    asm volatile("cp.async.commit_group;" ::: "memory")
#define CPA_WAIT0()     asm volatile("cp.async.wait_group 0;" ::: "memory")

__device__ int g_idx[256];

__global__ void prep_idx(const int* __restrict__ raw) {
    __shared__ int odd_nz;
    if (threadIdx.x == 0) odd_nz = 0;
    __syncthreads();
    if (threadIdx.x < 128) {
        if (raw[2 * threadIdx.x + 1] != 0) atomicAdd(&odd_nz, 1);
    }
    __syncthreads();
    bool is64 = (odd_nz == 0);
    g_idx[threadIdx.x] = is64 ? raw[2 * threadIdx.x] : raw[threadIdx.x];
}

__global__ __launch_bounds__(NT, 1)
void moe_tf32(const float* __restrict__ x,
              const float* __restrict__ gate_w,
              const float* __restrict__ W1,
              const float* __restrict__ b1,
              const float* __restrict__ W2,
              const float* __restrict__ b2,
              float* __restrict__ out)
{
    extern __shared__ float sm[];
    const uint32_t smb = smem_u32(sm);
    const int tid  = threadIdx.x;
    const int lane = tid & 31;
    const int warp = tid >> 5;
    const int wm   = warp >> 2;          // 0..3: M group (32 px)
    const int wn   = warp & 3;           // 0..3: N group
    const int g    = lane >> 2;
    const int t    = lane & 3;
    const int b    = blockIdx.y;
    const int p0   = blockIdx.x * TP;
    const int R0   = wm * 32;

    const int   e0 = g_idx[b * 2],           e1 = g_idx[b * 2 + 1];
    const float g0 = __ldg(&gate_w[b * 2]);
    const float g1 = __ldg(&gate_w[b * 2 + 1]);

    if (tid < 128)
        sm[OGB + tid] = g0 * __ldg(&b2[e0 * COUT + tid]) + g1 * __ldg(&b2[e1 * COUT + tid]);

    // ---- issue cp.async for W1 chunk 0 ----
    {
        const float* w1p = W1 + (size_t)e0 * CHID * CIN;
        #pragma unroll
        for (int i = 0; i < 4; i++) {
            int f = tid + i * NT;
            CPA16(smb + (uint32_t)(OW1 + (f >> 5) * 132 + (f & 31) * 4) * 4,
                  w1p + (size_t)(f >> 5) * CIN + (f & 31) * 4);
        }
        CPA_COMMIT();
    }

    // ---- stage x^T (transpose via 4x4 register tiles) ----
    {
        const float* xb = x + (size_t)b * CIN * HW + p0;
        const int q  = tid & 7;
        const int pg = (tid >> 3) & 31;
        const int hf = tid >> 8;
        const int pv = 4 * pg;
        #pragma unroll
        for (int cc = 0; cc < 2; cc++) {
            const int cg = 4 * (q + 8 * (2 * hf + cc));
            float4 v0, v1, v2, v3;
            if (p0 + pv < HW) {
                v0 = *(const float4*)(xb + (size_t)(cg + 0) * HW + pv);
                v1 = *(const float4*)(xb + (size_t)(cg + 1) * HW + pv);
                v2 = *(const float4*)(xb + (size_t)(cg + 2) * HW + pv);
                v3 = *(const float4*)(xb + (size_t)(cg + 3) * HW + pv);
            } else {
                v0 = v1 = v2 = v3 = make_float4(0.f, 0.f, 0.f, 0.f);
            }
            *(float4*)(sm + OXS + (pv + 0) * 132 + cg) =
                make_float4(tf32f(v0.x), tf32f(v1.x), tf32f(v2.x), tf32f(v3.x));
            *(float4*)(sm + OXS + (pv + 1) * 132 + cg) =
                make_float4(tf32f(v0.y), tf32f(v1.y), tf32f(v2.y), tf32f(v3.y));
            *(float4*)(sm + OXS + (pv + 2) * 132 + cg) =
                make_float4(tf32f(v0.z), tf32f(v1.z), tf32f(v2.z), tf32f(v3.z));
            *(float4*)(sm + OXS + (pv + 3) * 132 + cg) =
                make_float4(tf32f(v0.w), tf32f(v1.w), tf32f(v2.w), tf32f(v3.w));
        }
    }

    float acc2[2][4][4];
    #pragma unroll
    for (int m = 0; m < 2; m++)
        #pragma unroll
        for (int j = 0; j < 4; j++)
            #pragma unroll
            for (int q = 0; q < 4; q++) acc2[m][j][q] = 0.f;

    CPA_WAIT0();          // W1(0) landed
    __syncthreads();      // x + W1(0) visible

    #pragma unroll 1
    for (int it = 0; it < 8; it++) {
        const int   e    = (it < 4) ? e0 : e1;
        const int   j    = it & 3;
        const float gcur = (it < 4) ? g0 : g1;

        // ---- issue cp.async for W2(it) (lands during GEMM1) ----
        {
            const float* w2p = W2 + (size_t)e * COUT * CHID + j * 64;
            #pragma unroll
            for (int i = 0; i < 4; i++) {
                int f = tid + i * NT;
                CPA16(smb + (uint32_t)(OW2 + (f >> 4) * 68 + (f & 15) * 4) * 4,
                      w2p + (size_t)(f >> 4) * CHID + (f & 15) * 4);
            }
            CPA_COMMIT();
        }

        // ---- bias for this warp's 16-ch slice ----
        float biasv[4];
        {
            const float* b1p = b1 + e * CHID + j * 64 + wn * 16;
            #pragma unroll
            for (int j2 = 0; j2 < 2; j2++) {
                biasv[2 * j2]     = __ldg(b1p + 8 * j2 + 2 * t);
                biasv[2 * j2 + 1] = __ldg(b1p + 8 * j2 + 2 * t + 1);
            }
        }

        // ---- GEMM1: acc1[32 px][16 ch] = x @ W1chunk^T ----
        float acc1[2][2][4];
        #pragma unroll
        for (int m = 0; m < 2; m++)
            #pragma unroll
            for (int j2 = 0; j2 < 2; j2++)
                #pragma unroll
                for (int q = 0; q < 4; q++) acc1[m][j2][q] = 0.f;

        #pragma unroll 4
        for (int k = 0; k < 16; k++) {
            float a[2][4];
            #pragma unroll
            for (int m = 0; m < 2; m++) {
                int r = R0 + m * 16 + g;
                a[m][0] = sm[OXS + r * 132 + 8 * k + t];
                a[m][1] = sm[OXS + (r + 8) * 132 + 8 * k + t];
                a[m][2] = sm[OXS + r * 132 + 8 * k + t + 4];
                a[m][3] = sm[OXS + (r + 8) * 132 + 8 * k + t + 4];
            }
            #pragma unroll
            for (int j2 = 0; j2 < 2; j2++) {
                int n = wn * 16 + j2 * 8 + g;
                float b0 = tf32f(sm[OW1 + n * 132 + 8 * k + t]);
                float bq = tf32f(sm[OW1 + n * 132 + 8 * k + t + 4]);
                mma8(acc1[0][j2], a[0], b0, bq);
                mma8(acc1[1][j2], a[1], b0, bq);
            }
        }

        // ---- epilogue: bias + SiLU + gate -> h (tf32) ----
        #pragma unroll
        for (int m = 0; m < 2; m++) {
            #pragma unroll
            for (int j2 = 0; j2 < 2; j2++) {
                #pragma unroll
                for (int hi = 0; hi < 2; hi++) {
                    float v0 = acc1[m][j2][2 * hi]     + biasv[2 * j2];
                    float v1 = acc1[m][j2][2 * hi + 1] + biasv[2 * j2 + 1];
                    float h0 = gcur * (v0 / (1.f + __expf(-v0)));
                    float h1 = gcur * (v1 / (1.f + __expf(-v1)));
                    int row = R0 + m * 16 + g + 8 * hi;
                    int col = wn * 16 + j2 * 8 + 2 * t;
                    *(float2*)(sm + OHS + row * 68 + col) =
                        make_float2(tf32f(h0), tf32f(h1));
                }
            }
        }

        CPA_WAIT0();       // W2(it) landed (thread-local)
        __syncthreads();   // h + W2(it) visible; W1 reads quiesced

        // ---- issue cp.async for W1(it+1) (lands during GEMM2) ----
        if (it < 7) {
            const int en = (it + 1 >= 4) ? e1 : e0;
            const int jn = (it + 1) & 3;
            const float* w1p = W1 + (size_t)en * CHID * CIN + (size_t)(jn * 64) * CIN;
            #pragma unroll
            for (int i = 0; i < 4; i++) {
                int f = tid + i * NT;
                CPA16(smb + (uint32_t)(OW1 + (f >> 5) * 132 + (f & 31) * 4) * 4,
                      w1p + (size_t)(f >> 5) * CIN + (f & 31) * 4);
            }
            CPA_COMMIT();
        }

        // ---- GEMM2: acc2[32 px][32 oc] += h @ W2chunk^T ----
        #pragma unroll 4
        for (int k = 0; k < 8; k++) {
            float a[2][4];
            #pragma unroll
            for (int m = 0; m < 2; m++) {
                int r = R0 + m * 16 + g;
                a[m][0] = sm[OHS + r * 68 + 8 * k + t];
                a[m][1] = sm[OHS + (r + 8) * 68 + 8 * k + t];
                a[m][2] = sm[OHS + r * 68 + 8 * k + t + 4];
                a[m][3] = sm[OHS + (r + 8) * 68 + 8 * k + t + 4];
            }
            #pragma unroll
            for (int j2 = 0; j2 < 4; j2++) {
                int n = wn * 32 + j2 * 8 + g;
                float b0 = tf32f(sm[OW2 + n * 68 + 8 * k + t]);
                float bq = tf32f(sm[OW2 + n * 68 + 8 * k + t + 4]);
                mma8(acc2[0][j2], a[0], b0, bq);
                mma8(acc2[1][j2], a[1], b0, bq);
            }
        }

        if (it < 7) CPA_WAIT0();   // W1(it+1) landed (thread-local)
        __syncthreads();           // h + W2 free; W1(it+1) visible
    }

    // ---- final store: acc2 + gated b2 -> out ----
    {
        float* ob = out + (size_t)b * COUT * HW;
        #pragma unroll
        for (int m = 0; m < 2; m++) {
            #pragma unroll
            for (int hi = 0; hi < 2; hi++) {
                int pl = R0 + m * 16 + g + 8 * hi;
                if (p0 + pl < HW) {
                    #pragma unroll
                    for (int j2 = 0; j2 < 4; j2++) {
                        int oc = wn * 32 + j2 * 8 + 2 * t;
                        ob[(size_t)oc * HW + p0 + pl] =
                            acc2[m][j2][2 * hi] + sm[OGB + oc];
                        ob[(size_t)(oc + 1) * HW + p0 + pl] =
                            acc2[m][j2][2 * hi + 1] + sm[OGB + oc + 1];
                    }
                }
            }
        }
    }
}

extern "C" void kernel_launch(void* const* d_in, const int* in_sizes, int n_in,
                              void* d_out, int out_size) {
    const float* x   = (const float*)d_in[0];
    const float* wts = (const float*)d_in[1];
    const int*   idx = (const int*)d_in[2];
    const float* W1  = (const float*)d_in[3];
    const float* b1  = (const float*)d_in[4];
    const float* W2  = (const float*)d_in[5];
    const float* b2  = (const float*)d_in[6];
    float* out = (float*)d_out;
    (void)in_sizes; (void)n_in; (void)out_size;

    prep_idx<<<1, 256>>>(idx);

    cudaFuncSetAttribute(moe_tf32, cudaFuncAttributeMaxDynamicSharedMemorySize, SMB);
    dim3 grid(NTILE, 128);
    moe_tf32<<<grid, NT, SMB>>>(x, wts, W1, b1, W2, b2, out);
}